// round 5
// baseline (speedup 1.0000x reference)
#include <cuda_runtime.h>
#include <math.h>
#include <stdint.h>
#include <mma.h>

using namespace nvcuda;

// ---------------- problem constants ----------------
#define DIMC   384
#define HEADS  6
#define HD     64
#define HIDDEN 1536
#define BATCH  4
#define NX     2048
#define NY     256
#define MTOK   2304                 // tokens per batch (NX+NY)
#define TTOK   (BATCH*MTOK)         // 9216 total tokens
#define QKVN   (3*DIMC)             // 1152
#define ATT_SCALE 0.125f            // 64^-0.5
#define LN_EPS 1e-5f

// ---------------- scratch (static device globals; no allocation) ----------------
__device__ float g_catln[TTOK*DIMC];
__device__ float g_qkv  [TTOK*QKVN];
__device__ float g_attno[TTOK*DIMC];
__device__ float g_ln2  [TTOK*DIMC];
__device__ float g_fc1  [TTOK*HIDDEN];

// ---------------- LayerNorm over 384 channels, 1 token per block ----------------
__global__ void __launch_bounds__(128) ln_kernel(
    const float* __restrict__ px, const float* __restrict__ py,
    const float* __restrict__ w,  const float* __restrict__ bsh,
    float* __restrict__ out)
{
    int t   = blockIdx.x;
    int bb  = t / MTOK;
    int pos = t - bb * MTOK;
    const float* src = (pos < NX)
        ? px + ((size_t)(bb*NX + pos)) * DIMC
        : py + ((size_t)(bb*NY + pos - NX)) * DIMC;

    int tid = threadIdx.x;
    float v0 = src[tid], v1 = src[tid+128], v2 = src[tid+256];
    float s  = v0 + v1 + v2;
    float sq = v0*v0 + v1*v1 + v2*v2;
    #pragma unroll
    for (int o = 16; o; o >>= 1) {
        s  += __shfl_xor_sync(0xffffffffu, s,  o);
        sq += __shfl_xor_sync(0xffffffffu, sq, o);
    }
    __shared__ float sm[4], sm2[4], stat[2];
    int wi = tid >> 5;
    if ((tid & 31) == 0) { sm[wi] = s; sm2[wi] = sq; }
    __syncthreads();
    if (tid == 0) {
        float S = sm[0]+sm[1]+sm[2]+sm[3];
        float Q = sm2[0]+sm2[1]+sm2[2]+sm2[3];
        float mean = S * (1.0f/DIMC);
        float var  = Q * (1.0f/DIMC) - mean*mean;
        stat[0] = mean;
        stat[1] = rsqrtf(var + LN_EPS);
    }
    __syncthreads();
    float mean = stat[0], inv = stat[1];
    float* op = out + (size_t)t * DIMC;
    op[tid]     = (v0-mean)*inv*w[tid]     + bsh[tid];
    op[tid+128] = (v1-mean)*inv*w[tid+128] + bsh[tid+128];
    op[tid+256] = (v2-mean)*inv*w[tid+256] + bsh[tid+256];
}

// ---------------- per-element epilogue ----------------
// EPI 0: plain store (qkv, no bias)
// EPI 1: +bias +input residual -> scatter to outx/outy (proj)
// EPI 2: +bias, exact-erf GELU -> store (fc1)
// EPI 3: +bias +current out residual -> outx/outy in place (fc2)
template<int EPI>
__device__ __forceinline__ void epi_elem(int m, int n, float v, int N,
    const float* __restrict__ bias, float* __restrict__ C,
    const float* __restrict__ resx, const float* __restrict__ resy,
    float* __restrict__ outx, float* __restrict__ outy)
{
    if (EPI == 0) { C[(size_t)m*N + n] = v; return; }
    float bv = bias[n];
    if (EPI == 2) {
        float x = v + bv;
        C[(size_t)m*N + n] = 0.5f * x * (1.0f + erff(x * 0.70710678118654752f));
        return;
    }
    int bb  = m / MTOK;
    int pos = m - bb * MTOK;
    if (pos < NX) {
        size_t idx = ((size_t)(bb*NX + pos))*DIMC + n;
        float r = (EPI == 1) ? resx[idx] : outx[idx];
        outx[idx] = v + bv + r;
    } else {
        size_t idx = ((size_t)(bb*NY + pos - NX))*DIMC + n;
        float r = (EPI == 1) ? resy[idx] : outy[idx];
        outy[idx] = v + bv + r;
    }
}

// ---------------- wmma tf32 GEMM: C[M,N] = A[M,K] * W[N,K]^T ----------------
// block = 256 threads = 8 warps (4x2), each warp one 16x16 output tile,
// block tile 64x32. A/B fragments loaded directly from global (L1-served),
// accumulator -> per-warp smem tile (documented coords) -> epilogue.
template<int EPI>
__global__ void __launch_bounds__(256) gemm_wmma(
    const float* __restrict__ A, const float* __restrict__ W,
    const float* __restrict__ bias, float* __restrict__ C,
    int M, int N, int K,
    const float* __restrict__ resx, const float* __restrict__ resy,
    float* __restrict__ outx, float* __restrict__ outy)
{
    __shared__ float Ct[8][16*20];
    int w = threadIdx.x >> 5, lane = threadIdx.x & 31;
    int wm = w >> 1, wn = w & 1;
    int m0 = (blockIdx.y << 6) + wm*16;
    int n0 = (blockIdx.x << 5) + wn*16;

    wmma::fragment<wmma::matrix_a, 16, 16, 8, wmma::precision::tf32, wmma::row_major> af;
    wmma::fragment<wmma::matrix_b, 16, 16, 8, wmma::precision::tf32, wmma::col_major> bf;
    wmma::fragment<wmma::accumulator, 16, 16, 8, float> cf;
    wmma::fill_fragment(cf, 0.0f);

    const float* Ab = A + (size_t)m0 * K;
    const float* Wb = W + (size_t)n0 * K;

    for (int k = 0; k < K; k += 8) {
        wmma::load_matrix_sync(af, Ab + k, K);
        wmma::load_matrix_sync(bf, Wb + k, K);
        #pragma unroll
        for (int i = 0; i < af.num_elements; i++)
            af.x[i] = wmma::__float_to_tf32(af.x[i]);
        #pragma unroll
        for (int i = 0; i < bf.num_elements; i++)
            bf.x[i] = wmma::__float_to_tf32(bf.x[i]);
        wmma::mma_sync(cf, af, bf, cf);
    }

    wmma::store_matrix_sync(&Ct[w][0], cf, 20, wmma::mem_row_major);
    __syncwarp();

    int r  = lane >> 1;
    int cb = (lane & 1) << 3;
    #pragma unroll
    for (int j = 0; j < 8; j++) {
        float v = Ct[w][r*20 + cb + j];
        epi_elem<EPI>(m0 + r, n0 + cb + j, v, N, bias, C, resx, resy, outx, outy);
    }
}

// ---------------- flash-style attention, fp32 (R1-proven) ----------------
__global__ void __launch_bounds__(64) attn_kernel(
    const float* __restrict__ qkv, float* __restrict__ attno,
    int q_off, int k_len)
{
    __shared__ float Ks[64*64];
    __shared__ float Vs[64*64];
    __shared__ float S [64*64];
    int tid = threadIdx.x;
    int h = blockIdx.y, b = blockIdx.z;
    int qi = q_off + (blockIdx.x << 6) + tid;

    const float* qp = qkv + ((size_t)(b*MTOK + qi))*QKVN + h*HD;
    float4 q4[16];
    #pragma unroll
    for (int i = 0; i < 16; i++) {
        float4 t = *(const float4*)(qp + i*4);
        t.x *= ATT_SCALE; t.y *= ATT_SCALE; t.z *= ATT_SCALE; t.w *= ATT_SCALE;
        q4[i] = t;
    }
    float4 O4[16];
    #pragma unroll
    for (int i = 0; i < 16; i++) O4[i] = make_float4(0.f,0.f,0.f,0.f);
    float m = -INFINITY, l = 0.f;

    const float* kbase = qkv + ((size_t)b*MTOK)*QKVN + DIMC  + h*HD;
    const float* vbase = qkv + ((size_t)b*MTOK)*QKVN + 2*DIMC + h*HD;
    int r0 = tid >> 4;
    int c4 = tid & 15;

    for (int kt = 0; kt < k_len; kt += 64) {
        #pragma unroll
        for (int r = 0; r < 64; r += 4) {
            int row = r + r0;
            const float4* kp = (const float4*)(kbase + (size_t)(kt+row)*QKVN);
            const float4* vp = (const float4*)(vbase + (size_t)(kt+row)*QKVN);
            ((float4*)Ks)[row*16 + c4] = kp[c4];
            ((float4*)Vs)[row*16 + c4] = vp[c4];
        }
        __syncthreads();

        float tmax = m;
        #pragma unroll 4
        for (int j = 0; j < 64; j++) {
            const float4* kr = (const float4*)(Ks + j*64);
            float s = 0.f;
            #pragma unroll
            for (int i = 0; i < 16; i++) {
                float4 k4 = kr[i];
                s += q4[i].x*k4.x + q4[i].y*k4.y + q4[i].z*k4.z + q4[i].w*k4.w;
            }
            S[(tid<<6) + ((j + tid) & 63)] = s;
            tmax = fmaxf(tmax, s);
        }
        float corr = __expf(m - tmax);
        m = tmax;
        l *= corr;
        #pragma unroll
        for (int i = 0; i < 16; i++) {
            O4[i].x*=corr; O4[i].y*=corr; O4[i].z*=corr; O4[i].w*=corr;
        }
        #pragma unroll
        for (int j = 0; j < 64; j++) {
            int si = (tid<<6) + ((j + tid) & 63);
            float p = __expf(S[si] - m);
            l += p;
            S[si] = p;
        }
        #pragma unroll 2
        for (int j = 0; j < 64; j++) {
            float p = S[(tid<<6) + ((j + tid) & 63)];
            const float4* vr = (const float4*)(Vs + j*64);
            #pragma unroll
            for (int i = 0; i < 16; i++) {
                float4 v4 = vr[i];
                O4[i].x += p*v4.x; O4[i].y += p*v4.y; O4[i].z += p*v4.z; O4[i].w += p*v4.w;
            }
        }
        __syncthreads();
    }

    float inv = 1.f / l;
    float* op = attno + ((size_t)(b*MTOK + qi))*DIMC + h*HD;
    #pragma unroll
    for (int i = 0; i < 16; i++) {
        float4 o = O4[i];
        o.x*=inv; o.y*=inv; o.z*=inv; o.w*=inv;
        *(float4*)(op + i*4) = o;
    }
}

// ---------------- launch ----------------
extern "C" void kernel_launch(void* const* d_in, const int* in_sizes, int n_in,
                              void* d_out, int out_size)
{
    const float* x     = (const float*)d_in[0];
    const float* y     = (const float*)d_in[1];
    const float* n1w   = (const float*)d_in[2];
    const float* n1b   = (const float*)d_in[3];
    const float* n2w   = (const float*)d_in[4];
    const float* n2b   = (const float*)d_in[5];
    const float* qkvw  = (const float*)d_in[6];
    const float* projw = (const float*)d_in[7];
    const float* projb = (const float*)d_in[8];
    const float* fc1w  = (const float*)d_in[9];
    const float* fc1bb = (const float*)d_in[10];
    const float* fc2w  = (const float*)d_in[11];
    const float* fc2b  = (const float*)d_in[12];
    (void)in_sizes; (void)n_in; (void)out_size;

    float* outx = (float*)d_out;
    float* outy = outx + (size_t)BATCH*NX*DIMC;

    float *catln, *qkvb, *attno, *ln2o, *fc1o;
    cudaGetSymbolAddress((void**)&catln, g_catln);
    cudaGetSymbolAddress((void**)&qkvb,  g_qkv);
    cudaGetSymbolAddress((void**)&attno, g_attno);
    cudaGetSymbolAddress((void**)&ln2o,  g_ln2);
    cudaGetSymbolAddress((void**)&fc1o,  g_fc1);

    // 1) LN1 over concat(x, y)
    ln_kernel<<<TTOK, 128>>>(x, y, n1w, n1b, catln);
    // 2) fused QKV GEMM (no bias) — wmma tf32
    gemm_wmma<0><<<dim3(QKVN/32, TTOK/64), 256>>>(catln, qkvw, nullptr, qkvb,
        TTOK, QKVN, DIMC, nullptr, nullptr, nullptr, nullptr);
    // 3) x self-attention (fp32, R1-proven)
    attn_kernel<<<dim3(NX/64, HEADS, BATCH), 64>>>(qkvb, attno, 0, NX);
    // 4) y cross-attention
    attn_kernel<<<dim3(NY/64, HEADS, BATCH), 64>>>(qkvb, attno, NX, MTOK);
    // 5) output projection + bias + input residual -> d_out
    gemm_wmma<1><<<dim3(DIMC/32, TTOK/64), 256>>>(attno, projw, projb, nullptr,
        TTOK, DIMC, DIMC, x, y, outx, outy);
    // 6) LN2 over d_out
    ln_kernel<<<TTOK, 128>>>(outx, outy, n2w, n2b, ln2o);
    // 7) fc1 + bias + exact GELU
    gemm_wmma<2><<<dim3(HIDDEN/32, TTOK/64), 256>>>(ln2o, fc1w, fc1bb, fc1o,
        TTOK, HIDDEN, DIMC, nullptr, nullptr, nullptr, nullptr);
    // 8) fc2 + bias + residual (in place on d_out)
    gemm_wmma<3><<<dim3(DIMC/32, TTOK/64), 256>>>(fc1o, fc2w, fc2b, nullptr,
        TTOK, DIMC, HIDDEN, nullptr, nullptr, outx, outy);
}

// round 6
// speedup vs baseline: 2.9529x; 2.9529x over previous
#include <cuda_runtime.h>
#include <math.h>
#include <stdint.h>
#include <mma.h>

using namespace nvcuda;

// ---------------- problem constants ----------------
#define DIMC   384
#define HEADS  6
#define HD     64
#define HIDDEN 1536
#define BATCH  4
#define NX     2048
#define NY     256
#define MTOK   2304                 // tokens per batch (NX+NY)
#define TTOK   (BATCH*MTOK)         // 9216 total tokens
#define QKVN   (3*DIMC)             // 1152
#define ATT_SCALE 0.125f            // 64^-0.5
#define LN_EPS 1e-5f

#define ATS 68                      // attention smem row stride (64+4)
#define SMEM_ATTN (4*64*ATS*4)      // Ks, Vs, Ss, Os

// ---------------- scratch (static device globals; no allocation) ----------------
__device__ float g_catln[TTOK*DIMC];
__device__ float g_qkv  [TTOK*QKVN];
__device__ float g_attno[TTOK*DIMC];
__device__ float g_ln2  [TTOK*DIMC];
__device__ float g_fc1  [TTOK*HIDDEN];

// ---------------- tf32 rounding helper ----------------
__device__ __forceinline__ float f2tf32f(float f) {
    uint32_t u; asm("cvt.rna.tf32.f32 %0, %1;" : "=r"(u) : "f"(f));
    return __uint_as_float(u);
}

// ---------------- LayerNorm over 384 channels, 1 token per block ----------------
__global__ void __launch_bounds__(128) ln_kernel(
    const float* __restrict__ px, const float* __restrict__ py,
    const float* __restrict__ w,  const float* __restrict__ bsh,
    float* __restrict__ out)
{
    int t   = blockIdx.x;
    int bb  = t / MTOK;
    int pos = t - bb * MTOK;
    const float* src = (pos < NX)
        ? px + ((size_t)(bb*NX + pos)) * DIMC
        : py + ((size_t)(bb*NY + pos - NX)) * DIMC;

    int tid = threadIdx.x;
    float v0 = src[tid], v1 = src[tid+128], v2 = src[tid+256];
    float s  = v0 + v1 + v2;
    float sq = v0*v0 + v1*v1 + v2*v2;
    #pragma unroll
    for (int o = 16; o; o >>= 1) {
        s  += __shfl_xor_sync(0xffffffffu, s,  o);
        sq += __shfl_xor_sync(0xffffffffu, sq, o);
    }
    __shared__ float sm[4], sm2[4], stat[2];
    int wi = tid >> 5;
    if ((tid & 31) == 0) { sm[wi] = s; sm2[wi] = sq; }
    __syncthreads();
    if (tid == 0) {
        float S = sm[0]+sm[1]+sm[2]+sm[3];
        float Q = sm2[0]+sm2[1]+sm2[2]+sm2[3];
        float mean = S * (1.0f/DIMC);
        float var  = Q * (1.0f/DIMC) - mean*mean;
        stat[0] = mean;
        stat[1] = rsqrtf(var + LN_EPS);
    }
    __syncthreads();
    float mean = stat[0], inv = stat[1];
    float* op = out + (size_t)t * DIMC;
    op[tid]     = (v0-mean)*inv*w[tid]     + bsh[tid];
    op[tid+128] = (v1-mean)*inv*w[tid+128] + bsh[tid+128];
    op[tid+256] = (v2-mean)*inv*w[tid+256] + bsh[tid+256];
}

// ---------------- per-element epilogue ----------------
// EPI 0: plain store (qkv) | 1: +bias+input residual (proj)
// EPI 2: +bias+erf GELU (fc1) | 3: +bias+out residual (fc2)
template<int EPI>
__device__ __forceinline__ void epi_elem(int m, int n, float v, int N,
    const float* __restrict__ bias, float* __restrict__ C,
    const float* __restrict__ resx, const float* __restrict__ resy,
    float* __restrict__ outx, float* __restrict__ outy)
{
    if (EPI == 0) { C[(size_t)m*N + n] = v; return; }
    float bv = bias[n];
    if (EPI == 2) {
        float x = v + bv;
        C[(size_t)m*N + n] = 0.5f * x * (1.0f + erff(x * 0.70710678118654752f));
        return;
    }
    int bb  = m / MTOK;
    int pos = m - bb * MTOK;
    if (pos < NX) {
        size_t idx = ((size_t)(bb*NX + pos))*DIMC + n;
        float r = (EPI == 1) ? resx[idx] : outx[idx];
        outx[idx] = v + bv + r;
    } else {
        size_t idx = ((size_t)(bb*NY + pos - NX))*DIMC + n;
        float r = (EPI == 1) ? resy[idx] : outy[idx];
        outy[idx] = v + bv + r;
    }
}

// ---------------- staged wmma tf32 GEMM: C[M,N] = A[M,K] * W[N,K]^T ----------------
// block tile 128x64, 8 warps (4x2), warp tile 32x32, k-tile 32 in smem.
template<int EPI>
__global__ void __launch_bounds__(256) gemm_wmma(
    const float* __restrict__ A, const float* __restrict__ W,
    const float* __restrict__ bias, float* __restrict__ C,
    int M, int N, int K,
    const float* __restrict__ resx, const float* __restrict__ resy,
    float* __restrict__ outx, float* __restrict__ outy)
{
    __shared__ __align__(16) float As[128*36];
    __shared__ __align__(16) float Ws[64*36];
    __shared__ __align__(16) float Ct[8][16*20];

    int tid = threadIdx.x;
    int w = tid >> 5, lane = tid & 31;
    int wm = w >> 1, wn = w & 1;            // 4x2 warp grid
    int m0 = blockIdx.y << 7;
    int n0 = blockIdx.x << 6;

    wmma::fragment<wmma::accumulator, 16, 16, 8, float> acc[2][2];
    #pragma unroll
    for (int i = 0; i < 2; i++)
        #pragma unroll
        for (int j = 0; j < 2; j++) wmma::fill_fragment(acc[i][j], 0.0f);

    for (int k0 = 0; k0 < K; k0 += 32) {
        // stage A 128x32 (tf32-rounded)
        #pragma unroll
        for (int i = 0; i < 4; i++) {
            int idx = tid + i*256;
            int row = idx >> 3, c4 = (idx & 7) << 2;
            float4 av = *(const float4*)(A + (size_t)(m0+row)*K + k0 + c4);
            float* d = As + row*36 + c4;
            d[0]=f2tf32f(av.x); d[1]=f2tf32f(av.y); d[2]=f2tf32f(av.z); d[3]=f2tf32f(av.w);
        }
        // stage W 64x32
        #pragma unroll
        for (int i = 0; i < 2; i++) {
            int idx = tid + i*256;
            int row = idx >> 3, c4 = (idx & 7) << 2;
            float4 wv = *(const float4*)(W + (size_t)(n0+row)*K + k0 + c4);
            float* d = Ws + row*36 + c4;
            d[0]=f2tf32f(wv.x); d[1]=f2tf32f(wv.y); d[2]=f2tf32f(wv.z); d[3]=f2tf32f(wv.w);
        }
        __syncthreads();

        #pragma unroll
        for (int ks = 0; ks < 4; ks++) {
            int kb = ks << 3;
            wmma::fragment<wmma::matrix_a, 16, 16, 8, wmma::precision::tf32, wmma::row_major> af[2];
            wmma::fragment<wmma::matrix_b, 16, 16, 8, wmma::precision::tf32, wmma::col_major> bf[2];
            wmma::load_matrix_sync(af[0], As + (wm*32     )*36 + kb, 36);
            wmma::load_matrix_sync(af[1], As + (wm*32 + 16)*36 + kb, 36);
            wmma::load_matrix_sync(bf[0], Ws + (wn*32     )*36 + kb, 36);
            wmma::load_matrix_sync(bf[1], Ws + (wn*32 + 16)*36 + kb, 36);
            #pragma unroll
            for (int i = 0; i < 2; i++)
                #pragma unroll
                for (int j = 0; j < 2; j++)
                    wmma::mma_sync(acc[i][j], af[i], bf[j], acc[i][j]);
        }
        __syncthreads();
    }

    // epilogue via per-warp smem tile
    #pragma unroll
    for (int i = 0; i < 2; i++) {
        #pragma unroll
        for (int j = 0; j < 2; j++) {
            wmma::store_matrix_sync(&Ct[w][0], acc[i][j], 20, wmma::mem_row_major);
            __syncwarp();
            int r  = lane >> 1;
            int cb = (lane & 1) << 3;
            int mg = m0 + wm*32 + i*16 + r;
            int ng = n0 + wn*32 + j*16 + cb;
            #pragma unroll
            for (int q = 0; q < 8; q++)
                epi_elem<EPI>(mg, ng + q, Ct[w][r*20 + cb + q], N, bias, C, resx, resy, outx, outy);
            __syncwarp();
        }
    }
}

// ---------------- wmma tf32 flash attention ----------------
// 64 queries/block, 4 warps x 16 rows; Q frags in regs; S,O in smem.
__global__ void __launch_bounds__(128) attn_wmma(
    const float* __restrict__ qkv, float* __restrict__ attno,
    int q_off, int k_len)
{
    extern __shared__ __align__(16) float dyn[];
    float* Ks = dyn;                 // [64][ATS]
    float* Vs = Ks + 64*ATS;
    float* Ss = Vs + 64*ATS;         // S/P tile (per-warp 16-row slices)
    float* Os = Ss + 64*ATS;         // O accumulator fp32
    __shared__ float sm_m[64], sm_l[64];

    int tid = threadIdx.x, w = tid >> 5, lane = tid & 31;
    int h = blockIdx.y, b = blockIdx.z;
    int q0 = q_off + (blockIdx.x << 6);

    // stage Q (scaled, tf32) into Ss
    #pragma unroll
    for (int i = 0; i < 8; i++) {
        int idx = tid + i*128;
        int row = idx >> 4, c4 = (idx & 15) << 2;
        const float* qp = qkv + ((size_t)(b*MTOK + q0 + row))*QKVN + h*HD + c4;
        float4 v = *(const float4*)qp;
        float* d = Ss + row*ATS + c4;
        d[0]=f2tf32f(v.x*ATT_SCALE); d[1]=f2tf32f(v.y*ATT_SCALE);
        d[2]=f2tf32f(v.z*ATT_SCALE); d[3]=f2tf32f(v.w*ATT_SCALE);
    }
    __syncthreads();

    wmma::fragment<wmma::matrix_a, 16, 16, 8, wmma::precision::tf32, wmma::row_major> qa[8];
    #pragma unroll
    for (int kk = 0; kk < 8; kk++)
        wmma::load_matrix_sync(qa[kk], Ss + (w*16)*ATS + kk*8, ATS);

    // init O, m, l
    for (int i = tid; i < 64*ATS; i += 128) Os[i] = 0.f;
    if (tid < 64) { sm_m[tid] = -INFINITY; sm_l[tid] = 0.f; }
    __syncthreads();

    const float* kbase = qkv + ((size_t)b*MTOK)*QKVN + DIMC   + h*HD;
    const float* vbase = qkv + ((size_t)b*MTOK)*QKVN + 2*DIMC + h*HD;

    for (int kt = 0; kt < k_len; kt += 64) {
        // stage K, V (tf32)
        #pragma unroll
        for (int i = 0; i < 8; i++) {
            int idx = tid + i*128;
            int row = idx >> 4, c4 = (idx & 15) << 2;
            float4 kv = *(const float4*)(kbase + (size_t)(kt+row)*QKVN + c4);
            float4 vv = *(const float4*)(vbase + (size_t)(kt+row)*QKVN + c4);
            float* dk = Ks + row*ATS + c4;
            float* dv = Vs + row*ATS + c4;
            dk[0]=f2tf32f(kv.x); dk[1]=f2tf32f(kv.y); dk[2]=f2tf32f(kv.z); dk[3]=f2tf32f(kv.w);
            dv[0]=f2tf32f(vv.x); dv[1]=f2tf32f(vv.y); dv[2]=f2tf32f(vv.z); dv[3]=f2tf32f(vv.w);
        }
        __syncthreads();

        // S = Q @ K^T  (warp's 16 rows x 64 keys)
        #pragma unroll
        for (int j = 0; j < 4; j++) {
            wmma::fragment<wmma::accumulator, 16, 16, 8, float> sacc;
            wmma::fill_fragment(sacc, 0.0f);
            #pragma unroll
            for (int kk = 0; kk < 8; kk++) {
                wmma::fragment<wmma::matrix_b, 16, 16, 8, wmma::precision::tf32, wmma::col_major> kf;
                wmma::load_matrix_sync(kf, Ks + (j*16)*ATS + kk*8, ATS);
                wmma::mma_sync(sacc, qa[kk], kf, sacc);
            }
            wmma::store_matrix_sync(Ss + (w*16)*ATS + j*16, sacc, ATS, wmma::mem_row_major);
        }
        __syncwarp();

        // online softmax on warp's 16 rows (2 lanes per row, 32 cols each)
        {
            int r  = lane >> 1;
            int hf = lane & 1;
            int row = w*16 + r;
            float* srow = Ss + row*ATS + hf*32;
            float mold = sm_m[row];
            float tmax = mold;
            #pragma unroll
            for (int c = 0; c < 32; c++) tmax = fmaxf(tmax, srow[c]);
            tmax = fmaxf(tmax, __shfl_xor_sync(0xffffffffu, tmax, 1));
            float corr = __expf(mold - tmax);
            float psum = 0.f;
            #pragma unroll
            for (int c = 0; c < 32; c++) {
                float p = __expf(srow[c] - tmax);
                psum += p;
                srow[c] = f2tf32f(p);
            }
            psum += __shfl_xor_sync(0xffffffffu, psum, 1);
            if (hf == 0) {
                sm_m[row] = tmax;
                sm_l[row] = sm_l[row]*corr + psum;
            }
            // rescale O row
            float* orow = Os + row*ATS + hf*32;
            #pragma unroll
            for (int c = 0; c < 32; c++) orow[c] *= corr;
        }
        __syncwarp();

        // O += P @ V
        wmma::fragment<wmma::matrix_a, 16, 16, 8, wmma::precision::tf32, wmma::row_major> pa[8];
        #pragma unroll
        for (int kk = 0; kk < 8; kk++)
            wmma::load_matrix_sync(pa[kk], Ss + (w*16)*ATS + kk*8, ATS);
        #pragma unroll
        for (int j = 0; j < 4; j++) {
            wmma::fragment<wmma::accumulator, 16, 16, 8, float> oacc;
            wmma::load_matrix_sync(oacc, Os + (w*16)*ATS + j*16, ATS, wmma::mem_row_major);
            #pragma unroll
            for (int kk = 0; kk < 8; kk++) {
                wmma::fragment<wmma::matrix_b, 16, 16, 8, wmma::precision::tf32, wmma::row_major> vf;
                wmma::load_matrix_sync(vf, Vs + (kk*8)*ATS + j*16, ATS);
                wmma::mma_sync(oacc, pa[kk], vf, oacc);
            }
            wmma::store_matrix_sync(Os + (w*16)*ATS + j*16, oacc, ATS, wmma::mem_row_major);
        }
        __syncthreads();
    }

    // write normalized O
    {
        int r  = tid >> 1;
        int hf = tid & 1;
        float inv = 1.f / sm_l[r];
        const float* orow = Os + r*ATS + hf*32;
        float* op = attno + ((size_t)(b*MTOK + q0 + r))*DIMC + h*HD + hf*32;
        #pragma unroll
        for (int c4 = 0; c4 < 8; c4++) {
            float4 o = *(const float4*)(orow + c4*4);
            o.x*=inv; o.y*=inv; o.z*=inv; o.w*=inv;
            *(float4*)(op + c4*4) = o;
        }
    }
}

// ---------------- launch ----------------
extern "C" void kernel_launch(void* const* d_in, const int* in_sizes, int n_in,
                              void* d_out, int out_size)
{
    const float* x     = (const float*)d_in[0];
    const float* y     = (const float*)d_in[1];
    const float* n1w   = (const float*)d_in[2];
    const float* n1b   = (const float*)d_in[3];
    const float* n2w   = (const float*)d_in[4];
    const float* n2b   = (const float*)d_in[5];
    const float* qkvw  = (const float*)d_in[6];
    const float* projw = (const float*)d_in[7];
    const float* projb = (const float*)d_in[8];
    const float* fc1w  = (const float*)d_in[9];
    const float* fc1bb = (const float*)d_in[10];
    const float* fc2w  = (const float*)d_in[11];
    const float* fc2b  = (const float*)d_in[12];
    (void)in_sizes; (void)n_in; (void)out_size;

    float* outx = (float*)d_out;
    float* outy = outx + (size_t)BATCH*NX*DIMC;

    float *catln, *qkvb, *attno, *ln2o, *fc1o;
    cudaGetSymbolAddress((void**)&catln, g_catln);
    cudaGetSymbolAddress((void**)&qkvb,  g_qkv);
    cudaGetSymbolAddress((void**)&attno, g_attno);
    cudaGetSymbolAddress((void**)&ln2o,  g_ln2);
    cudaGetSymbolAddress((void**)&fc1o,  g_fc1);

    cudaFuncSetAttribute(attn_wmma, cudaFuncAttributeMaxDynamicSharedMemorySize, SMEM_ATTN);

    // 1) LN1 over concat(x, y)
    ln_kernel<<<TTOK, 128>>>(x, y, n1w, n1b, catln);
    // 2) fused QKV GEMM — staged wmma tf32
    gemm_wmma<0><<<dim3(QKVN/64, TTOK/128), 256>>>(catln, qkvw, nullptr, qkvb,
        TTOK, QKVN, DIMC, nullptr, nullptr, nullptr, nullptr);
    // 3) x self-attention (wmma tf32)
    attn_wmma<<<dim3(NX/64, HEADS, BATCH), 128, SMEM_ATTN>>>(qkvb, attno, 0, NX);
    // 4) y cross-attention
    attn_wmma<<<dim3(NY/64, HEADS, BATCH), 128, SMEM_ATTN>>>(qkvb, attno, NX, MTOK);
    // 5) output projection + bias + input residual -> d_out
    gemm_wmma<1><<<dim3(DIMC/64, TTOK/128), 256>>>(attno, projw, projb, nullptr,
        TTOK, DIMC, DIMC, x, y, outx, outy);
    // 6) LN2 over d_out
    ln_kernel<<<TTOK, 128>>>(outx, outy, n2w, n2b, ln2o);
    // 7) fc1 + bias + exact GELU
    gemm_wmma<2><<<dim3(HIDDEN/64, TTOK/128), 256>>>(ln2o, fc1w, fc1bb, fc1o,
        TTOK, HIDDEN, DIMC, nullptr, nullptr, nullptr, nullptr);
    // 8) fc2 + bias + residual (in place on d_out)
    gemm_wmma<3><<<dim3(DIMC/64, TTOK/128), 256>>>(fc1o, fc2w, fc2b, nullptr,
        TTOK, DIMC, HIDDEN, nullptr, nullptr, outx, outy);
}